// round 4
// baseline (speedup 1.0000x reference)
#include <cuda_runtime.h>
#include <cstdint>
#include <cstddef>

// ---------------- problem constants ----------------
#define BATCH 16384
#define JNT   17
#define FIN   256
#define FOUT  256
#define MROWS (BATCH * JNT)          // 278528 = 2176 * 128
#define KTOT  (3 * FIN)              // 768

// GEMM tiling
#define BM 128
#define BN 256
#define BK 32
#define NKIT (KTOT / BK)             // 24 k-iterations (t = part*8 + fc)
#define ASTRIDE 40                   // words per A smem row
#define BSTRIDE 40                   // words per B smem row

// smem word-offset layout
#define SADJ_OFF 0                   // 289 words (adj 17x17)
#define AZ_OFF   320                 // 128*40 = 5120 words (single z stage)
#define X_OFF    (AZ_OFF + BM * ASTRIDE)          // 5440
#define XSLW     (9 * JNT * 32)                   // 4896 words per x-slice buf
#define B_OFF    (X_OFF + 3 * XSLW)               // 20128
#define BSTGW    (BN * BSTRIDE)                   // 10240 words per B stage
#define SMEM_WORDS (B_OFF + 3 * BSTGW)            // 50848
#define SMEM_BYTES (SMEM_WORDS * 4)               // 203392

// ---------------- device scratch ----------------
__device__ float g_wb[(size_t)NKIT * BN * 32];   // Wcat prepacked, unpadded (786KB)

// ---------------- helpers ----------------
__device__ __forceinline__ uint32_t smem_u32(const void* p) {
    uint32_t a;
    asm("{ .reg .u64 t; cvta.to.shared.u64 t, %1; cvt.u32.u64 %0, t; }" : "=r"(a) : "l"(p));
    return a;
}
__device__ __forceinline__ float rtf32(float v) {
    uint32_t r;
    asm("cvt.rn.tf32.f32 %0, %1;" : "=r"(r) : "f"(v));
    return __uint_as_float(r);
}
__device__ __forceinline__ void cp16(uint32_t dst, const void* src) {
    asm volatile("cp.async.cg.shared.global [%0], [%1], 16;" :: "r"(dst), "l"(src));
}
#define CP_COMMIT() asm volatile("cp.async.commit_group;" ::: "memory")
#define CP_WAIT1()  asm volatile("cp.async.wait_group 1;" ::: "memory")

__device__ __forceinline__ void mma_tf32(float* d, uint32_t a0, uint32_t a1,
                                         uint32_t a2, uint32_t a3,
                                         uint32_t b0, uint32_t b1) {
    asm volatile(
        "mma.sync.aligned.m16n8k8.row.col.f32.tf32.tf32.f32 "
        "{%0,%1,%2,%3}, {%4,%5,%6,%7}, {%8,%9}, {%0,%1,%2,%3};"
        : "+f"(d[0]), "+f"(d[1]), "+f"(d[2]), "+f"(d[3])
        : "r"(a0), "r"(a1), "r"(a2), "r"(a3), "r"(b0), "r"(b1));
}

// ---------------- kernel 0: prepack Wcat (tf32-rounded, k-interleaved, unpadded) ----------------
__global__ void __launch_bounds__(256) wprep_kernel(const float* __restrict__ W) {
    int idx = blockIdx.x * 256 + threadIdx.x;      // 24*256*32 = 196608
    int p = idx & 31;
    int n = (idx >> 5) & 255;
    int t = idx >> 13;
    int s = p >> 3, q = p & 7;
    int w = (q >> 1) + ((q & 1) << 2);             // inverse k-interleave perm
    int k = t * 32 + s * 8 + w;
    g_wb[idx] = rtf32(W[k * FOUT + n]);
}

// ---------------- z-stage compute (aggregation fused into A producer) ----------------
// unit u in [0,288): bl = u>>5 (window batch), f = u&31 (local k / feature).
// Computes z[row = wbase + bl*17 + i][f] for i = 0..16 of the given part.
template <int PART>
__device__ __forceinline__ void z_unit(const float* __restrict__ sadj,
                                       const float* __restrict__ xb,
                                       float* __restrict__ Az,
                                       int u, int wbase) {
    const int bl = u >> 5, f = u & 31;
    float xr[JNT];
    #pragma unroll
    for (int j = 0; j < JNT; j++) xr[j] = xb[(bl * JNT + j) * 32 + f];
    const int pc = ((f >> 3) << 3) + ((f & 3) << 1) + ((f >> 2) & 1);
    const int lr0 = wbase + bl * JNT;
    #pragma unroll
    for (int i = 0; i < JNT; i++) {
        float v = 0.0f;
        if (PART == 0) v = sadj[i * JNT + i] * xr[i];
        if (PART == 1) {
            #pragma unroll
            for (int j = i + 1; j < JNT; j++) v += sadj[i * JNT + j] * xr[j];
        }
        if (PART == 2) {
            #pragma unroll
            for (int j = 0; j < i; j++) v += sadj[i * JNT + j] * xr[j];
        }
        const int lr = lr0 + i;
        if (lr >= 0 && lr < BM) Az[lr * ASTRIDE + pc] = rtf32(v);
    }
}

template <int PART>
__device__ __forceinline__ void z_phase(const float* sadj, const float* xb,
                                        float* Az, int tid, int wbase) {
    const int w = tid >> 5, l = tid & 31;
    z_unit<PART>(sadj, xb, Az, w * 36 + l, wbase);
    if (l < 4) z_unit<PART>(sadj, xb, Az, w * 36 + 32 + l, wbase);
}

// ---------------- fused GEMM: out = (agg(x, adj)) @ Wcat + bias ----------------
__device__ __forceinline__ void load_inputs(float* sm, uint32_t sb, int t, int buf,
                                            int tid, const float* x, int b0) {
    // x-slice for (part = t>>3, fc = t&7): 153 rows x 128B
    const int fbase = (t & 7) * 32;
    uint32_t xd = sb + (X_OFF + buf * XSLW) * 4;
    #pragma unroll
    for (int q = 0; q < 5; q++) {
        int id = tid + q * 256;
        if (id < 153 * 8) {
            int rowi = id >> 3, ck = id & 7;
            int bl = rowi / JNT;
            int j  = rowi - bl * JNT;
            int bg = b0 + bl; if (bg > BATCH - 1) bg = BATCH - 1;
            const float* src = x + ((size_t)(bg * JNT + j) << 8) + fbase + ck * 4;
            cp16(xd + (rowi * 32 + ck * 4) * 4, src);
        }
    }
    // B stage t: 2048 16B chunks, contiguous src, stride-40 dst rows
    const float* wb = g_wb + (size_t)t * (BN * 32);
    uint32_t bd = sb + (B_OFF + buf * BSTGW) * 4;
    #pragma unroll
    for (int q = 0; q < 8; q++) {
        int id = tid + q * 256;
        int row = id >> 3, ck = id & 7;
        cp16(bd + (row * BSTRIDE + ck * 4) * 4, wb + id * 4);
    }
}

__global__ void __launch_bounds__(256, 1) gemm_fused(const float* __restrict__ x,
                                                     const float* __restrict__ adj,
                                                     const float* __restrict__ bias,
                                                     float* __restrict__ out) {
    extern __shared__ float sm[];
    const uint32_t sb = smem_u32(sm);
    const int tid = threadIdx.x;
    const int wid = tid >> 5;
    const int lane = tid & 31;
    const int warp_m = wid & 1;
    const int warp_n = wid >> 1;
    const int r = lane >> 2;
    const int c = lane & 3;

    const int mbase = blockIdx.x * BM;
    const int b0 = mbase / JNT;
    const int wbase = b0 * JNT - mbase;      // in (-17, 0]

    // adj into smem
    for (int i = tid; i < JNT * JNT; i += 256) sm[SADJ_OFF + i] = adj[i];

    float acc[128];
    #pragma unroll
    for (int i = 0; i < 128; i++) acc[i] = 0.0f;

    // prologue: prefetch t=0, t=1
    load_inputs(sm, sb, 0, 0, tid, x, b0); CP_COMMIT();
    load_inputs(sm, sb, 1, 1, tid, x, b0); CP_COMMIT();

    float* Az = sm + AZ_OFF;
    int buf = 0;                             // t % 3

    for (int t = 0; t < NKIT; t++) {
        CP_WAIT1();
        __syncthreads();                     // slice t arrived; prev mma done (Az free)

        // z stage (aggregation) for iter t
        const float* xb = sm + X_OFF + buf * XSLW;
        const int part = t >> 3;
        if (part == 0)      z_phase<0>(sm + SADJ_OFF, xb, Az, tid, wbase);
        else if (part == 1) z_phase<1>(sm + SADJ_OFF, xb, Az, tid, wbase);
        else                z_phase<2>(sm + SADJ_OFF, xb, Az, tid, wbase);
        __syncthreads();                     // z ready

        // mma phase
        const float* Bs = sm + B_OFF + buf * BSTGW;
        #pragma unroll
        for (int s = 0; s < 4; s++) {
            uint2 aF[4][2];
            #pragma unroll
            for (int mt = 0; mt < 4; mt++) {
                const float* ap = Az + (warp_m * 64 + mt * 16 + r) * ASTRIDE + s * 8 + 2 * c;
                aF[mt][0] = *(const uint2*)ap;
                aF[mt][1] = *(const uint2*)(ap + 8 * ASTRIDE);
            }
            uint2 bF[8];
            #pragma unroll
            for (int nt = 0; nt < 8; nt++) {
                const float* bp = Bs + (warp_n * 64 + nt * 8 + r) * BSTRIDE + s * 8 + 2 * c;
                bF[nt] = *(const uint2*)bp;
            }
            #pragma unroll
            for (int mt = 0; mt < 4; mt++)
                #pragma unroll
                for (int nt = 0; nt < 8; nt++)
                    mma_tf32(&acc[(mt * 8 + nt) * 4],
                             aF[mt][0].x, aF[mt][1].x, aF[mt][0].y, aF[mt][1].y,
                             bF[nt].x, bF[nt].y);
        }

        // prefetch t+2 into buffer (t+2)%3 (nobody touches it: last read at t-1)
        int nbuf = buf + 2; if (nbuf >= 3) nbuf -= 3;
        if (t + 2 < NKIT) load_inputs(sm, sb, t + 2, nbuf, tid, x, b0);
        CP_COMMIT();

        buf = buf + 1; if (buf == 3) buf = 0;
    }

    // epilogue: + bias, write out
    #pragma unroll
    for (int mt = 0; mt < 4; mt++) {
        size_t gm = (size_t)mbase + warp_m * 64 + mt * 16 + r;
        float* o0 = out + gm * FOUT;
        #pragma unroll
        for (int nt = 0; nt < 8; nt++) {
            int col = warp_n * 64 + nt * 8 + 2 * c;
            float b0v = __ldg(bias + col), b1v = __ldg(bias + col + 1);
            const float* a = &acc[(mt * 8 + nt) * 4];
            *(float2*)(o0 + col)            = make_float2(a[0] + b0v, a[1] + b1v);
            *(float2*)(o0 + 8 * FOUT + col) = make_float2(a[2] + b0v, a[3] + b1v);
        }
    }
}

// ---------------- launch ----------------
extern "C" void kernel_launch(void* const* d_in, const int* in_sizes, int n_in,
                              void* d_out, int out_size) {
    const float* x    = (const float*)d_in[0];   // [16384,17,256]
    const float* W    = (const float*)d_in[1];   // [3,256,256]
    const float* adj  = (const float*)d_in[2];   // [17,17]
    const float* bias = (const float*)d_in[3];   // [256]
    float* out = (float*)d_out;                  // [16384,17,256]

    cudaFuncSetAttribute(gemm_fused, cudaFuncAttributeMaxDynamicSharedMemorySize, SMEM_BYTES);

    wprep_kernel<<<(NKIT * BN * 32) / 256, 256>>>(W);
    gemm_fused<<<MROWS / BM, 256, SMEM_BYTES>>>(x, adj, bias, out);
}

// round 5
// speedup vs baseline: 2.9299x; 2.9299x over previous
#include <cuda_runtime.h>
#include <cuda_fp16.h>
#include <cstdint>
#include <cstddef>

// ---------------- problem constants ----------------
#define BATCH 16384
#define JNT   17
#define FIN   256
#define FOUT  256
#define MROWS (BATCH * JNT)          // 278528 = 2176 * 128
#define KTOT  (3 * FIN)              // 768
#define PROW  384                    // uint32 (fp16-pairs) per z row

// GEMM tiling (fp16: BK=64 k = 32 pairs per iter)
#define BM 128
#define BN 256
#define BK 64
#define NKIT (KTOT / BK)             // 12
#define NSTAGE 3
#define ASTRIDE 40                   // uint32 per A smem row (32 pairs + 8 pad)
#define BSTRIDE 40                   // uint32 per B smem row
#define ASZW (BM * ASTRIDE)          // 5120 uint32
#define BSZW (BN * BSTRIDE)          // 10240 uint32
#define STGW (ASZW + BSZW)           // 15360 uint32 per stage
#define SMEM_BYTES (NSTAGE * STGW * 4)   // 184320

// ---------------- device scratch ----------------
__device__ uint32_t g_z[(size_t)MROWS * PROW];       // z fp16-pairs, interleaved (~428MB)
__device__ uint32_t g_wb[(size_t)NKIT * BN * 32];    // Wcat prepacked fp16 (~393KB)

// ---------------- helpers ----------------
__device__ __forceinline__ uint32_t smem_u32(const void* p) {
    uint32_t a;
    asm("{ .reg .u64 t; cvta.to.shared.u64 t, %1; cvt.u32.u64 %0, t; }" : "=r"(a) : "l"(p));
    return a;
}
__device__ __forceinline__ void cp16(uint32_t dst, const void* src) {
    asm volatile("cp.async.cg.shared.global [%0], [%1], 16;" :: "r"(dst), "l"(src));
}
#define CP_COMMIT() asm volatile("cp.async.commit_group;" ::: "memory")
#define CP_WAIT1()  asm volatile("cp.async.wait_group 1;" ::: "memory")

// fp16 mma m16n8k16, fp32 accumulate (arch-neutral, sm_80+)
__device__ __forceinline__ void mma_f16(float* d, uint32_t a0, uint32_t a1,
                                        uint32_t a2, uint32_t a3,
                                        uint32_t b0, uint32_t b1) {
    asm volatile(
        "mma.sync.aligned.m16n8k16.row.col.f32.f16.f16.f32 "
        "{%0,%1,%2,%3}, {%4,%5,%6,%7}, {%8,%9}, {%0,%1,%2,%3};"
        : "+f"(d[0]), "+f"(d[1]), "+f"(d[2]), "+f"(d[3])
        : "r"(a0), "r"(a1), "r"(a2), "r"(a3), "r"(b0), "r"(b1));
}

__device__ __forceinline__ uint32_t pack2(float lo, float hi) {
    __half2 h = __floats2half2_rn(lo, hi);
    return *reinterpret_cast<uint32_t*>(&h);
}

// pair-interleave within each 8-pair group: pair q -> slot (q&3)*2 + (q>>2)
// so (pair c, pair c+4) are adjacent -> one LDS.64 per fragment half.

// ---------------- kernel 0: prepack Wcat fp16 ----------------
// g_wb[t][n][slot]: slot s holds pairs (k = 2P, 2P+1) of column n,
// P = t*32 + (s>>3)*8 + invperm(s&7).
__global__ void __launch_bounds__(256) wprep_kernel(const float* __restrict__ W) {
    int idx = blockIdx.x * 256 + threadIdx.x;      // 12*256*32 = 98304
    int s = idx & 31;
    int n = (idx >> 5) & 255;
    int t = idx >> 13;
    int sp = s & 7;
    int q = (sp >> 1) + ((sp & 1) << 2);           // invperm
    int P = t * 32 + (s >> 3) * 8 + q;
    int k0 = 2 * P;
    g_wb[idx] = pack2(W[k0 * FOUT + n], W[(k0 + 1) * FOUT + n]);
}

// ---------------- kernel 1: aggregation -> z (fp16 pairs, interleaved) ----------------
// block handles 2 batches; thread (sub = tid>>7, p = tid&127) -> features 2p, 2p+1.
__global__ void __launch_bounds__(256) agg_kernel(const float* __restrict__ x,
                                                  const float* __restrict__ adj) {
    __shared__ float sx[2 * JNT * FIN];
    __shared__ float sadj[JNT * JNT];
    const int tid = threadIdx.x;
    const int b0 = blockIdx.x * 2;

    const float4* xs = (const float4*)(x + (size_t)b0 * JNT * FIN);
    float4* sd = (float4*)sx;
    for (int t = tid; t < 2 * JNT * FIN / 4; t += 256) sd[t] = xs[t];
    for (int t = tid; t < JNT * JNT; t += 256) sadj[t] = adj[t];
    __syncthreads();

    const int sub = tid >> 7;
    const int p = tid & 127;
    const float* xb = sx + sub * JNT * FIN;

    float xa[JNT], xc[JNT];
    #pragma unroll
    for (int j = 0; j < JNT; j++) {
        float2 v = ((const float2*)(xb + j * FIN))[p];
        xa[j] = v.x; xc[j] = v.y;
    }

    const int q = p & 7;
    const int sl = (p >> 3) * 8 + ((q & 3) * 2 + (q >> 2));    // slot within 128-pair part
    uint32_t* zr = g_z + (size_t)(b0 + sub) * JNT * PROW;

    #pragma unroll
    for (int i = 0; i < JNT; i++) {
        float d0 = sadj[i * JNT + i] * xa[i];
        float d1 = sadj[i * JNT + i] * xc[i];
        float s1a = 0.f, s1c = 0.f, s2a = 0.f, s2c = 0.f;
        #pragma unroll
        for (int j = 0; j < JNT; j++) {
            float a = sadj[i * JNT + j];
            if (j > i) { s1a += a * xa[j]; s1c += a * xc[j]; }
            if (j < i) { s2a += a * xa[j]; s2c += a * xc[j]; }
        }
        uint32_t* zi = zr + i * PROW;
        zi[sl]       = pack2(d0, d1);
        zi[128 + sl] = pack2(s1a, s1c);
        zi[256 + sl] = pack2(s2a, s2c);
    }
}

// ---------------- kernel 2: GEMM  out = z @ Wcat + bias  (fp16 mma) ----------------
__device__ __forceinline__ void load_stage(uint32_t sb, int t, int s, int tid, size_t mbase) {
    // A: z rows [mbase..mbase+127], slots [t*32, t*32+32) -> 128B/row, 1024 chunks
    const uint32_t* za = g_z + mbase * PROW + t * 32;
    uint32_t as = sb + (uint32_t)s * STGW * 4;
    #pragma unroll
    for (int qq = 0; qq < 4; qq++) {
        int id = tid + qq * 256;
        int row = id >> 3, ck = id & 7;
        cp16(as + (row * ASTRIDE + ck * 4) * 4, za + (size_t)row * PROW + ck * 4);
    }
    // B: prepacked stage t, 2048 chunks, contiguous src, stride-40 dst rows
    const uint32_t* wb = g_wb + (size_t)t * (BN * 32);
    uint32_t bs = sb + ((uint32_t)s * STGW + ASZW) * 4;
    #pragma unroll
    for (int qq = 0; qq < 8; qq++) {
        int id = tid + qq * 256;
        int row = id >> 3, ck = id & 7;
        cp16(bs + (row * BSTRIDE + ck * 4) * 4, wb + id * 4);
    }
}

__global__ void __launch_bounds__(256, 1) gemm_kernel(float* __restrict__ out,
                                                      const float* __restrict__ bias) {
    extern __shared__ uint32_t sm[];
    const uint32_t sb = smem_u32(sm);
    const int tid = threadIdx.x;
    const int wid = tid >> 5;
    const int lane = tid & 31;
    const int warp_m = wid & 1;
    const int warp_n = wid >> 1;
    const int r = lane >> 2;
    const int c = lane & 3;
    const size_t mbase = (size_t)blockIdx.x * BM;

    float acc[128];
    #pragma unroll
    for (int i = 0; i < 128; i++) acc[i] = 0.0f;

    load_stage(sb, 0, 0, tid, mbase); CP_COMMIT();
    load_stage(sb, 1, 1, tid, mbase); CP_COMMIT();

    for (int t = 0; t < NKIT; t++) {
        CP_WAIT1();
        __syncthreads();
        if (t + NSTAGE - 1 < NKIT)
            load_stage(sb, t + NSTAGE - 1, (t + NSTAGE - 1) % NSTAGE, tid, mbase);
        CP_COMMIT();

        const uint32_t* As = sm + (t % NSTAGE) * STGW;
        const uint32_t* Bs = As + ASZW;

        #pragma unroll
        for (int s = 0; s < 4; s++) {                  // 4 k-steps of 16
            uint2 aF[4][2];
            #pragma unroll
            for (int mt = 0; mt < 4; mt++) {
                const uint32_t* ap = As + (warp_m * 64 + mt * 16 + r) * ASTRIDE + s * 8 + 2 * c;
                aF[mt][0] = *(const uint2*)ap;                    // (R0,R2): pairs c, c+4, row r
                aF[mt][1] = *(const uint2*)(ap + 8 * ASTRIDE);    // (R1,R3): row r+8
            }
            uint2 bF[8];
            #pragma unroll
            for (int nt = 0; nt < 8; nt++) {
                const uint32_t* bp = Bs + (warp_n * 64 + nt * 8 + r) * BSTRIDE + s * 8 + 2 * c;
                bF[nt] = *(const uint2*)bp;                       // (b0,b1)
            }
            #pragma unroll
            for (int mt = 0; mt < 4; mt++)
                #pragma unroll
                for (int nt = 0; nt < 8; nt++)
                    mma_f16(&acc[(mt * 8 + nt) * 4],
                            aF[mt][0].x, aF[mt][1].x, aF[mt][0].y, aF[mt][1].y,
                            bF[nt].x, bF[nt].y);
        }
        __syncthreads();
    }

    // epilogue: + bias, write fp32 out
    #pragma unroll
    for (int mt = 0; mt < 4; mt++) {
        size_t gm = mbase + warp_m * 64 + mt * 16 + r;
        float* o0 = out + gm * FOUT;
        #pragma unroll
        for (int nt = 0; nt < 8; nt++) {
            int col = warp_n * 64 + nt * 8 + 2 * c;
            float b0 = __ldg(bias + col), b1 = __ldg(bias + col + 1);
            const float* a = &acc[(mt * 8 + nt) * 4];
            *(float2*)(o0 + col)            = make_float2(a[0] + b0, a[1] + b1);
            *(float2*)(o0 + 8 * FOUT + col) = make_float2(a[2] + b0, a[3] + b1);
        }
    }
}

// ---------------- launch ----------------
extern "C" void kernel_launch(void* const* d_in, const int* in_sizes, int n_in,
                              void* d_out, int out_size) {
    const float* x    = (const float*)d_in[0];   // [16384,17,256]
    const float* W    = (const float*)d_in[1];   // [3,256,256] == Wcat[768,256]
    const float* adj  = (const float*)d_in[2];   // [17,17]
    const float* bias = (const float*)d_in[3];   // [256]
    float* out = (float*)d_out;                  // [16384,17,256]

    cudaFuncSetAttribute(gemm_kernel, cudaFuncAttributeMaxDynamicSharedMemorySize, SMEM_BYTES);

    wprep_kernel<<<(NKIT * BN * 32) / 256, 256>>>(W);
    agg_kernel<<<BATCH / 2, 256>>>(x, adj);
    gemm_kernel<<<MROWS / BM, 256, SMEM_BYTES>>>(out, bias);
}